// round 7
// baseline (speedup 1.0000x reference)
#include <cuda_runtime.h>
#include <cuda_bf16.h>
#include <math.h>
#include <cstdint>

#define N_NODES 50000
#define N_EDGES 800000
#define F 128
#define NCLS 16

#define PITCH 136                        // bf16 elems per pitched row (272 B)
#define TILE_BYTES (128 * PITCH * 2)     // 34816 B per 128x128 bf16 tile
#define TILES 391                        // ceil(50000/128)
#define GGRID 148                        // persistent grid

// ---------------- device scratch ----------------
__device__ float g_bufA[N_NODES * F];
__device__ float g_bufB[N_NODES * F];
__device__ float g_dinv[N_NODES];
__device__ __align__(16) int g_cnt[N_NODES];
__device__ __align__(16) int g_cur[N_NODES];
__device__ int   g_rowstart[N_NODES + 1];
__device__ unsigned long long g_tstate[16];
__device__ int   g_csr[N_EDGES];
__device__ __align__(16) char g_Wimg[5 * 2 * TILE_BYTES];

// ---------------- helpers ----------------
__device__ __forceinline__ uint32_t smem_u32(const void* p) {
    uint32_t a;
    asm("{ .reg .u64 t; cvta.to.shared.u64 t, %1; cvt.u32.u64 %0, t; }" : "=r"(a) : "l"(p));
    return a;
}
__device__ __forceinline__ void cp16(uint32_t saddr, const void* gaddr) {
    asm volatile("cp.async.cg.shared.global [%0], [%1], 16;" :: "r"(saddr), "l"(gaddr));
}
__device__ __forceinline__ void cp16z(uint32_t saddr, const void* gaddr, bool valid) {
    int sz = valid ? 16 : 0;
    asm volatile("cp.async.cg.shared.global [%0], [%1], 16, %2;" :: "r"(saddr), "l"(gaddr), "r"(sz));
}
__device__ __forceinline__ void ldsm_x4(uint32_t* r, uint32_t addr) {
    asm volatile("ldmatrix.sync.aligned.m8n8.x4.shared.b16 {%0,%1,%2,%3}, [%4];"
                 : "=r"(r[0]), "=r"(r[1]), "=r"(r[2]), "=r"(r[3]) : "r"(addr));
}
__device__ __forceinline__ void ldsm_x4t(uint32_t* r, uint32_t addr) {
    asm volatile("ldmatrix.sync.aligned.m8n8.x4.trans.shared.b16 {%0,%1,%2,%3}, [%4];"
                 : "=r"(r[0]), "=r"(r[1]), "=r"(r[2]), "=r"(r[3]) : "r"(addr));
}
__device__ __forceinline__ void mma16816(float* d, const uint32_t* a, const uint32_t* b) {
    asm volatile(
        "mma.sync.aligned.m16n8k16.row.col.f32.bf16.bf16.f32 "
        "{%0,%1,%2,%3}, {%4,%5,%6,%7}, {%8,%9}, {%0,%1,%2,%3};"
        : "+f"(d[0]), "+f"(d[1]), "+f"(d[2]), "+f"(d[3])
        : "r"(a[0]), "r"(a[1]), "r"(a[2]), "r"(a[3]), "r"(b[0]), "r"(b[1]));
}
// split fp32x4 -> bf16 hi/lo packed uint2s
__device__ __forceinline__ void split4(float4 v, uint2& hp, uint2& lp) {
    __nv_bfloat16 h0 = __float2bfloat16(v.x);
    __nv_bfloat16 h1 = __float2bfloat16(v.y);
    __nv_bfloat16 h2 = __float2bfloat16(v.z);
    __nv_bfloat16 h3 = __float2bfloat16(v.w);
    __nv_bfloat16 l0 = __float2bfloat16(v.x - __bfloat162float(h0));
    __nv_bfloat16 l1 = __float2bfloat16(v.y - __bfloat162float(h1));
    __nv_bfloat16 l2 = __float2bfloat16(v.z - __bfloat162float(h2));
    __nv_bfloat16 l3 = __float2bfloat16(v.w - __bfloat162float(h3));
    __nv_bfloat162 hA = __halves2bfloat162(h0, h1);
    __nv_bfloat162 hB = __halves2bfloat162(h2, h3);
    __nv_bfloat162 lA = __halves2bfloat162(l0, l1);
    __nv_bfloat162 lB = __halves2bfloat162(l2, l3);
    hp.x = *(uint32_t*)&hA; hp.y = *(uint32_t*)&hB;
    lp.x = *(uint32_t*)&lA; lp.y = *(uint32_t*)&lB;
}

// ---------------- kernel 0: weight split + scratch clear ----------------
__global__ void k_wconv_clear(const float* __restrict__ W0, const float* __restrict__ W1,
                              const float* __restrict__ W2, const float* __restrict__ W3,
                              const float* __restrict__ W4) {
    int b = blockIdx.x;
    int tid = threadIdx.x;
    if (b < 5) {
        const float* Ws[5] = {W0, W1, W2, W3, W4};
        const float* W = Ws[b];
        char* hi = &g_Wimg[b * 2 * TILE_BYTES];
        char* lo = hi + TILE_BYTES;
        for (int idx = tid; idx < 16384; idx += 256) {
            int k = idx >> 7, n = idx & 127;
            float v = W[k * 128 + n];
            __nv_bfloat16 h = __float2bfloat16(v);
            __nv_bfloat16 l = __float2bfloat16(v - __bfloat162float(h));
            uint32_t off = (uint32_t)(k * PITCH + n) * 2;
            *(__nv_bfloat16*)(hi + off) = h;
            *(__nv_bfloat16*)(lo + off) = l;
        }
    } else if (b < 55) {
        int i = (b - 5) * 256 + tid;
        if (i < 12500) ((int4*)g_cnt)[i] = make_int4(0, 0, 0, 0);
    } else if (b < 105) {
        int i = (b - 55) * 256 + tid;
        if (i < 12500) ((int4*)g_cur)[i] = make_int4(0, 0, 0, 0);
    } else {
        if (tid < 16) g_tstate[tid] = 0ULL;
    }
}

// ---------------- kernel 1: degree count ----------------
__global__ void k_count(const int* __restrict__ ei, int e) {
    int i = blockIdx.x * blockDim.x + threadIdx.x;
    if (i < e) atomicAdd(&g_cnt[ei[N_EDGES + i]], 1);
}

// ---------------- kernel 2: single-pass scan + dinv ----------------
__global__ __launch_bounds__(1024) void k_scan(int n, int nb) {
    __shared__ int wsums[32];
    __shared__ int sh_total;
    __shared__ int sh_prefix;
    int tid = threadIdx.x, bid = blockIdx.x;
    int lane = tid & 31, w = tid >> 5;
    int base = bid * 4096 + tid * 4;
    int c0 = 0, c1 = 0, c2 = 0, c3 = 0;
    if (base < n) {
        int4 v = *(const int4*)&g_cnt[base];
        c0 = v.x; c1 = v.y; c2 = v.z; c3 = v.w;
        g_dinv[base]     = rsqrtf((float)(c0 + 1));
        g_dinv[base + 1] = rsqrtf((float)(c1 + 1));
        g_dinv[base + 2] = rsqrtf((float)(c2 + 1));
        g_dinv[base + 3] = rsqrtf((float)(c3 + 1));
    }
    int s = c0 + c1 + c2 + c3;
    int x = s;
#pragma unroll
    for (int o = 1; o < 32; o <<= 1) {
        int y = __shfl_up_sync(0xffffffffu, x, o);
        if (lane >= o) x += y;
    }
    if (lane == 31) wsums[w] = x;
    __syncthreads();
    if (w == 0) {
        int ws = wsums[lane];
        int xs = ws;
#pragma unroll
        for (int o = 1; o < 32; o <<= 1) {
            int y = __shfl_up_sync(0xffffffffu, xs, o);
            if (lane >= o) xs += y;
        }
        wsums[lane] = xs - ws;
        if (lane == 31) sh_total = xs;
    }
    __syncthreads();
    int excl = x - s + wsums[w];
    int total = sh_total;
    if (tid == 0) {
        int pre = 0;
        if (bid == 0) {
            atomicExch(&g_tstate[0], (2ULL << 32) | (unsigned)total);
        } else {
            atomicExch(&g_tstate[bid], (1ULL << 32) | (unsigned)total);
            int i = bid - 1;
            while (1) {
                unsigned long long v = atomicAdd(&g_tstate[i], 0ULL);
                unsigned f = (unsigned)(v >> 32);
                if (f == 0) continue;
                pre += (int)(unsigned)v;
                if (f == 2) break;
                i--;
            }
            atomicExch(&g_tstate[bid], (2ULL << 32) | (unsigned)(pre + total));
        }
        sh_prefix = pre;
        if (bid == nb - 1) g_rowstart[n] = pre + total;
    }
    __syncthreads();
    int run = sh_prefix + excl;
    if (base < n) {
        g_rowstart[base]     = run;
        g_rowstart[base + 1] = run + c0;
        g_rowstart[base + 2] = run + c0 + c1;
        g_rowstart[base + 3] = run + c0 + c1 + c2;
    }
}

// ---------------- kernel 3: CSR fill ----------------
__global__ void k_fill(const int* __restrict__ ei, int e) {
    int i = blockIdx.x * blockDim.x + threadIdx.x;
    if (i < e) {
        int d = ei[N_EDGES + i];
        int p = atomicAdd(&g_cur[d], 1);
        g_csr[g_rowstart[d] + p] = ei[i];
    }
}

// ================= fused GCN layer: C = relu((Â H) W + b) =================
// smem: bias | A buf0 hi/lo | A buf1 hi/lo | W hi/lo
#define GC_BIAS 0
#define GC_A    1024
#define GC_W    (GC_A + 4 * TILE_BYTES)       // 140288
#define GC_TOTAL (GC_W + 2 * TILE_BYTES)      // 209920

__global__ __launch_bounds__(256, 1) void k_gcn(const float* __restrict__ H,
                                                const char* __restrict__ Wimg,
                                                const float* __restrict__ bias,
                                                float* __restrict__ C, int M) {
    extern __shared__ char smem[];
    uint32_t sb = smem_u32(smem);
    int tid = threadIdx.x;
    int wid = tid >> 5, lane = tid & 31;
    const float4* H4 = (const float4*)H;

    if (tid < 32) ((float4*)(smem + GC_BIAS))[tid] = ((const float4*)bias)[tid];

    // W hi/lo resident for whole kernel
    for (int i = tid; i < (2 * TILE_BYTES) / 16; i += 256)
        cp16(sb + GC_W + i * 16, Wimg + i * 16);
    asm volatile("cp.async.commit_group;");

    // gather lambda-ish: aggregate 16 rows for this warp into buffer `boff`
    auto gather = [&](int t, int boff) {
        int rowBase = t * 128;
#pragma unroll 1
        for (int i = 0; i < 16; i++) {
            int rr = wid * 16 + i;
            int grow = rowBase + rr;
            float4 acc = make_float4(0.f, 0.f, 0.f, 0.f);
            if (grow < M) {
                float di = g_dinv[grow];
                float4 h = H4[(size_t)grow * 32 + lane];
                acc.x = di * h.x; acc.y = di * h.y; acc.z = di * h.z; acc.w = di * h.w;
                int beg = g_rowstart[grow], end = g_rowstart[grow + 1];
                int j = beg;
                for (; j + 3 < end; j += 4) {
                    int s0 = g_csr[j], s1 = g_csr[j + 1], s2 = g_csr[j + 2], s3 = g_csr[j + 3];
                    float w0 = g_dinv[s0], w1 = g_dinv[s1], w2 = g_dinv[s2], w3 = g_dinv[s3];
                    float4 v0 = H4[(size_t)s0 * 32 + lane];
                    float4 v1 = H4[(size_t)s1 * 32 + lane];
                    float4 v2 = H4[(size_t)s2 * 32 + lane];
                    float4 v3 = H4[(size_t)s3 * 32 + lane];
                    acc.x += w0 * v0.x + w1 * v1.x + w2 * v2.x + w3 * v3.x;
                    acc.y += w0 * v0.y + w1 * v1.y + w2 * v2.y + w3 * v3.y;
                    acc.z += w0 * v0.z + w1 * v1.z + w2 * v2.z + w3 * v3.z;
                    acc.w += w0 * v0.w + w1 * v1.w + w2 * v2.w + w3 * v3.w;
                }
                for (; j < end; j++) {
                    int s0 = g_csr[j];
                    float w0 = g_dinv[s0];
                    float4 v0 = H4[(size_t)s0 * 32 + lane];
                    acc.x += w0 * v0.x; acc.y += w0 * v0.y;
                    acc.z += w0 * v0.z; acc.w += w0 * v0.w;
                }
                acc.x *= di; acc.y *= di; acc.z *= di; acc.w *= di;
            }
            uint2 hp, lp;
            split4(acc, hp, lp);
            uint32_t off = (uint32_t)(rr * PITCH + lane * 4) * 2;
            *(uint2*)(smem + boff + off) = hp;
            *(uint2*)(smem + boff + TILE_BYTES + off) = lp;
        }
    };

    // prologue: gather first tile into buf0
    int t = blockIdx.x;
    if (t < TILES) gather(t, GC_A);
    asm volatile("cp.async.wait_group 0;" ::: "memory");

    // per-lane fragment addressing (relative to a hi-buffer base)
    int wm = wid >> 1, wn = wid & 1;
    int rsub = (lane & 7) + ((lane & 8) ? 8 : 0);
    int csub = (lane & 16) ? 8 : 0;
    uint32_t aoff0 = (uint32_t)((wm * 32 + rsub) * PITCH + csub) * 2;
    uint32_t aoff1 = aoff0 + (uint32_t)(16 * PITCH * 2);
    uint32_t wbase = sb + GC_W + (uint32_t)(rsub * PITCH + wn * 64 + csub) * 2;
    const uint32_t WLO_OFF = TILE_BYTES;
    const uint32_t KROW = 16 * PITCH * 2;

    int p = 0;
    for (; t < TILES; t += GGRID) {
        __syncthreads();   // buf[p] gather complete; prior MMA reads done

        int tn = t + GGRID;
        if (tn < TILES) gather(tn, GC_A + (1 - p) * 2 * TILE_BYTES);

        uint32_t ab = sb + GC_A + p * 2 * TILE_BYTES;
        uint32_t a0 = ab + aoff0, a1 = ab + aoff1;
        uint32_t l0a = a0 + TILE_BYTES, l1a = a1 + TILE_BYTES;

        float acc[2][4][8];
#pragma unroll
        for (int m = 0; m < 2; m++)
#pragma unroll
            for (int g = 0; g < 4; g++)
#pragma unroll
                for (int j = 0; j < 8; j++) acc[m][g][j] = 0.f;

#pragma unroll
        for (int kc = 0; kc < 8; kc++) {
            uint32_t ah[2][4], al[2][4];
            ldsm_x4(ah[0], a0 + kc * 32);
            ldsm_x4(ah[1], a1 + kc * 32);
            ldsm_x4(al[0], l0a + kc * 32);
            ldsm_x4(al[1], l1a + kc * 32);
            uint32_t bh[4][4], bl[4][4];
#pragma unroll
            for (int g = 0; g < 4; g++) ldsm_x4t(bh[g], wbase + kc * KROW + g * 32);
#pragma unroll
            for (int g = 0; g < 4; g++) ldsm_x4t(bl[g], wbase + WLO_OFF + kc * KROW + g * 32);
#pragma unroll
            for (int g = 0; g < 4; g++)
#pragma unroll
                for (int m = 0; m < 2; m++) {
                    mma16816(&acc[m][g][0], ah[m], &bh[g][0]);
                    mma16816(&acc[m][g][4], ah[m], &bh[g][2]);
                }
#pragma unroll
            for (int g = 0; g < 4; g++)
#pragma unroll
                for (int m = 0; m < 2; m++) {
                    mma16816(&acc[m][g][0], ah[m], &bl[g][0]);
                    mma16816(&acc[m][g][4], ah[m], &bl[g][2]);
                }
#pragma unroll
            for (int g = 0; g < 4; g++)
#pragma unroll
                for (int m = 0; m < 2; m++) {
                    mma16816(&acc[m][g][0], al[m], &bh[g][0]);
                    mma16816(&acc[m][g][4], al[m], &bh[g][2]);
                }
        }

        // epilogue: bias + relu -> gmem
        const float* bias_s = (const float*)(smem + GC_BIAS);
        int rq = lane >> 2;
        int cq = (lane & 3) * 2;
        int rowBase = t * 128;
#pragma unroll
        for (int m = 0; m < 2; m++) {
            int r0 = rowBase + wm * 32 + m * 16 + rq;
#pragma unroll
            for (int g = 0; g < 4; g++) {
#pragma unroll
                for (int h = 0; h < 2; h++) {
                    int c = wn * 64 + g * 16 + h * 8 + cq;
                    float bx = bias_s[c], by = bias_s[c + 1];
                    float* base = &acc[m][g][h * 4];
                    if (r0 < M) {
                        float2 v;
                        v.x = fmaxf(base[0] + bx, 0.f);
                        v.y = fmaxf(base[1] + by, 0.f);
                        *(float2*)&C[(size_t)r0 * 128 + c] = v;
                    }
                    if (r0 + 8 < M) {
                        float2 v;
                        v.x = fmaxf(base[2] + bx, 0.f);
                        v.y = fmaxf(base[3] + by, 0.f);
                        *(float2*)&C[(size_t)(r0 + 8) * 128 + c] = v;
                    }
                }
            }
        }
        p ^= 1;
    }
}

// ================= MLP GEMM (persistent, A-prefetch), MODE1 fuses head =================
#define SM_BIAS  0
#define SM_WF3   512
#define SM_BF3   (512 + 8192)
#define SM_AHI   8768
#define SM_ALO   (SM_AHI + TILE_BYTES)
#define SM_WHI   (SM_ALO + TILE_BYTES)
#define SM_WLO   (SM_WHI + TILE_BYTES)
#define SM_STAGE (SM_WLO + TILE_BYTES)
#define SM_TOTAL (SM_STAGE + 65536)

template<int MODE>
__global__ __launch_bounds__(256, 1) void k_gemm_tc(
    const float* __restrict__ A, const char* __restrict__ Wimg,
    const float* __restrict__ bias, float* __restrict__ C, int M,
    const float* __restrict__ Wf3, const float* __restrict__ bf3,
    float* __restrict__ out)
{
    extern __shared__ char smem[];
    uint32_t sb = smem_u32(smem);
    int tid = threadIdx.x;
    int wid = tid >> 5, lane = tid & 31;

    if (tid < 32) ((float4*)(smem + SM_BIAS))[tid] = ((const float4*)bias)[tid];
    if (MODE == 1) {
        for (int i = tid; i < 512; i += 256)
            ((float4*)(smem + SM_WF3))[i] = ((const float4*)Wf3)[i];
        if (tid < 16) ((float*)(smem + SM_BF3))[tid] = bf3[tid];
    }

    for (int i = tid; i < (2 * TILE_BYTES) / 16; i += 256)
        cp16(sb + SM_WHI + i * 16, Wimg + i * 16);
    asm volatile("cp.async.commit_group;");

    int t = blockIdx.x;
    {
        int rowBase = t * 128;
        for (int i = tid; i < 4096; i += 256) {
            int row = i >> 5, col = i & 31;
            int grow = rowBase + row;
            cp16z(sb + SM_STAGE + i * 16, A + (size_t)grow * 128 + col * 4, grow < M);
        }
    }
    asm volatile("cp.async.commit_group;");

    int wm = wid >> 1, wn = wid & 1;
    int rsub = (lane & 7) + ((lane & 8) ? 8 : 0);
    int csub = (lane & 16) ? 8 : 0;
    uint32_t a0 = sb + SM_AHI + (uint32_t)((wm * 32 + rsub) * PITCH + csub) * 2;
    uint32_t a1 = a0 + (uint32_t)(16 * PITCH * 2);
    uint32_t l0a = a0 + TILE_BYTES;
    uint32_t l1a = a1 + TILE_BYTES;
    uint32_t wbase = sb + SM_WHI + (uint32_t)(rsub * PITCH + wn * 64 + csub) * 2;
    const uint32_t WLO_OFF = TILE_BYTES;
    const uint32_t KROW = 16 * PITCH * 2;

    for (; t < TILES; t += GGRID) {
        int rowBase = t * 128;
        asm volatile("cp.async.wait_group 0;" ::: "memory");
        __syncthreads();

        for (int idx = tid; idx < 4096; idx += 256) {
            int row = idx >> 5;
            int k = (idx & 31) * 4;
            float4 v = *(const float4*)(smem + SM_STAGE + (size_t)(row * 128 + k) * 4);
            uint2 hp, lp;
            split4(v, hp, lp);
            uint32_t off = (uint32_t)(row * PITCH + k) * 2;
            *(uint2*)(smem + SM_AHI + off) = hp;
            *(uint2*)(smem + SM_ALO + off) = lp;
        }
        __syncthreads();

        int tn = t + GGRID;
        if (tn < TILES) {
            int rb2 = tn * 128;
            for (int i = tid; i < 4096; i += 256) {
                int row = i >> 5, col = i & 31;
                int grow = rb2 + row;
                cp16z(sb + SM_STAGE + i * 16, A + (size_t)grow * 128 + col * 4, grow < M);
            }
        }
        asm volatile("cp.async.commit_group;");

        float acc[2][4][8];
#pragma unroll
        for (int m = 0; m < 2; m++)
#pragma unroll
            for (int g = 0; g < 4; g++)
#pragma unroll
                for (int j = 0; j < 8; j++) acc[m][g][j] = 0.f;

#pragma unroll
        for (int kc = 0; kc < 8; kc++) {
            uint32_t ah[2][4], al[2][4];
            ldsm_x4(ah[0], a0 + kc * 32);
            ldsm_x4(ah[1], a1 + kc * 32);
            ldsm_x4(al[0], l0a + kc * 32);
            ldsm_x4(al[1], l1a + kc * 32);
            uint32_t bh[4][4], bl[4][4];
#pragma unroll
            for (int g = 0; g < 4; g++) ldsm_x4t(bh[g], wbase + kc * KROW + g * 32);
#pragma unroll
            for (int g = 0; g < 4; g++) ldsm_x4t(bl[g], wbase + WLO_OFF + kc * KROW + g * 32);
#pragma unroll
            for (int g = 0; g < 4; g++)
#pragma unroll
                for (int m = 0; m < 2; m++) {
                    mma16816(&acc[m][g][0], ah[m], &bh[g][0]);
                    mma16816(&acc[m][g][4], ah[m], &bh[g][2]);
                }
#pragma unroll
            for (int g = 0; g < 4; g++)
#pragma unroll
                for (int m = 0; m < 2; m++) {
                    mma16816(&acc[m][g][0], ah[m], &bl[g][0]);
                    mma16816(&acc[m][g][4], ah[m], &bl[g][2]);
                }
#pragma unroll
            for (int g = 0; g < 4; g++)
#pragma unroll
                for (int m = 0; m < 2; m++) {
                    mma16816(&acc[m][g][0], al[m], &bh[g][0]);
                    mma16816(&acc[m][g][4], al[m], &bh[g][2]);
                }
        }

        const float* bias_s = (const float*)(smem + SM_BIAS);
        int rq = lane >> 2;
        int cq = (lane & 3) * 2;

        if (MODE == 0) {
#pragma unroll
            for (int m = 0; m < 2; m++) {
                int r0 = rowBase + wm * 32 + m * 16 + rq;
#pragma unroll
                for (int g = 0; g < 4; g++) {
#pragma unroll
                    for (int h = 0; h < 2; h++) {
                        int c = wn * 64 + g * 16 + h * 8 + cq;
                        float bx = bias_s[c], by = bias_s[c + 1];
                        float* base = &acc[m][g][h * 4];
                        if (r0 < M) {
                            float2 v;
                            v.x = fmaxf(base[0] + bx, 0.f);
                            v.y = fmaxf(base[1] + by, 0.f);
                            *(float2*)&C[(size_t)r0 * 128 + c] = v;
                        }
                        if (r0 + 8 < M) {
                            float2 v;
                            v.x = fmaxf(base[2] + bx, 0.f);
                            v.y = fmaxf(base[3] + by, 0.f);
                            *(float2*)&C[(size_t)(r0 + 8) * 128 + c] = v;
                        }
                    }
                }
            }
        } else {
            __syncthreads();   // all ldsm reads of A tiles done before Ys overwrites
            float* Ys = (float*)(smem + SM_AHI);
#pragma unroll
            for (int m = 0; m < 2; m++) {
                int rl = wm * 32 + m * 16 + rq;
#pragma unroll
                for (int g = 0; g < 4; g++) {
#pragma unroll
                    for (int h = 0; h < 2; h++) {
                        int c = wn * 64 + g * 16 + h * 8 + cq;
                        float bx = bias_s[c], by = bias_s[c + 1];
                        float* base = &acc[m][g][h * 4];
                        float2 v;
                        v.x = fmaxf(base[0] + bx, 0.f);
                        v.y = fmaxf(base[1] + by, 0.f);
                        *(float2*)&Ys[rl * 128 + c] = v;
                        float2 v2;
                        v2.x = fmaxf(base[2] + bx, 0.f);
                        v2.y = fmaxf(base[3] + by, 0.f);
                        *(float2*)&Ys[(rl + 8) * 128 + c] = v2;
                    }
                }
            }
            __syncthreads();

            const float* Wfs = (const float*)(smem + SM_WF3);
            const float* bfs = (const float*)(smem + SM_BF3);
            int hr = tid >> 4, hc = tid & 15;
#pragma unroll
            for (int pz = 0; pz < 8; pz++) {
                int r = pz * 16 + hr;
                float a2 = bfs[hc];
#pragma unroll 16
                for (int k = 0; k < 128; k++) a2 += Ys[r * 128 + k] * Wfs[k * 16 + hc];
                float mx = a2;
#pragma unroll
                for (int o = 8; o > 0; o >>= 1) mx = fmaxf(mx, __shfl_xor_sync(0xffffffffu, mx, o));
                float e = expf(a2 - mx);
                float ssum = e;
#pragma unroll
                for (int o = 8; o > 0; o >>= 1) ssum += __shfl_xor_sync(0xffffffffu, ssum, o);
                float res = a2 - mx - logf(ssum);
                int grow = rowBase + r;
                if (grow < M) out[(size_t)grow * 16 + hc] = res;
            }
        }
    }
}

// ---------------- launch ----------------
extern "C" void kernel_launch(void* const* d_in, const int* in_sizes, int n_in,
                              void* d_out, int out_size) {
    const float* x   = (const float*)d_in[0];
    const int*   ei  = (const int*)d_in[1];
    const float* W1  = (const float*)d_in[3];
    const float* b1  = (const float*)d_in[4];
    const float* W2  = (const float*)d_in[5];
    const float* b2  = (const float*)d_in[6];
    const float* W3  = (const float*)d_in[7];
    const float* b3  = (const float*)d_in[8];
    const float* Wf1 = (const float*)d_in[9];
    const float* bf1 = (const float*)d_in[10];
    const float* Wf2 = (const float*)d_in[11];
    const float* bf2 = (const float*)d_in[12];
    const float* Wf3 = (const float*)d_in[13];
    const float* bf3 = (const float*)d_in[14];
    float* out = (float*)d_out;

    const int N = N_NODES;
    const int E = N_EDGES;

    float* bufA; float* bufB; char* wimg;
    cudaGetSymbolAddress((void**)&bufA, g_bufA);
    cudaGetSymbolAddress((void**)&bufB, g_bufB);
    cudaGetSymbolAddress((void**)&wimg, g_Wimg);

    static int attr_done = 0;
    if (!attr_done) {
        cudaFuncSetAttribute(k_gcn, cudaFuncAttributeMaxDynamicSharedMemorySize, GC_TOTAL);
        cudaFuncSetAttribute(k_gemm_tc<0>, cudaFuncAttributeMaxDynamicSharedMemorySize, SM_TOTAL);
        cudaFuncSetAttribute(k_gemm_tc<1>, cudaFuncAttributeMaxDynamicSharedMemorySize, SM_TOTAL);
        attr_done = 1;
    }

    const size_t IMG = 2 * (size_t)TILE_BYTES;

    k_wconv_clear<<<106, 256>>>(W1, W2, W3, Wf1, Wf2);            // 0
    k_count<<<(E + 255) / 256, 256>>>(ei, E);                     // 1
    k_scan<<<13, 1024>>>(N, 13);                                  // 2
    k_fill<<<(E + 255) / 256, 256>>>(ei, E);                      // 3

    k_gcn<<<GGRID, 256, GC_TOTAL>>>(x,    wimg + 0 * IMG, b1, bufA, N);    // 4
    k_gcn<<<GGRID, 256, GC_TOTAL>>>(bufA, wimg + 1 * IMG, b2, bufB, N);    // 5 <- ncu?
    k_gcn<<<GGRID, 256, GC_TOTAL>>>(bufB, wimg + 2 * IMG, b3, bufA, N);    // 6
    k_gemm_tc<0><<<GGRID, 256, SM_TOTAL>>>(bufA, wimg + 3 * IMG, bf1, bufB, N,
                                           nullptr, nullptr, nullptr);      // 7
    k_gemm_tc<1><<<GGRID, 256, SM_TOTAL>>>(bufB, wimg + 4 * IMG, bf2, nullptr, N,
                                           Wf3, bf3, out);                  // 8
}

// round 8
// speedup vs baseline: 1.7533x; 1.7533x over previous
#include <cuda_runtime.h>
#include <cuda_bf16.h>
#include <cuda_fp16.h>
#include <math.h>
#include <cstdint>

#define N_NODES 50000
#define N_EDGES 800000
#define F 128
#define NCLS 16

#define PITCH 136                        // bf16 elems per pitched row (272 B)
#define TILE_BYTES (128 * PITCH * 2)     // 34816 B per 128x128 bf16 tile
#define TILES 391                        // ceil(50000/128)
#define GGRID 148                        // persistent GEMM grid

// ---------------- device scratch ----------------
__device__ __half g_H0[N_NODES * F];               // fp16 feature buffer A (12.8MB)
__device__ __half g_H1[N_NODES * F];               // fp16 feature buffer B
__device__ __align__(16) char g_T [TILES * 2 * TILE_BYTES];   // split-tile buffer (27.2MB)
__device__ __align__(16) char g_T2[TILES * 2 * TILE_BYTES];   // split-tile buffer 2
__device__ float g_dinv[N_NODES];
__device__ __align__(16) int g_cnt[N_NODES];
__device__ __align__(16) int g_cur[N_NODES];
__device__ int   g_rowstart[N_NODES + 1];
__device__ unsigned long long g_tstate[16];
__device__ int   g_csr[N_EDGES];
__device__ __align__(16) char g_Wimg[5 * 2 * TILE_BYTES];

// ---------------- helpers ----------------
__device__ __forceinline__ uint32_t smem_u32(const void* p) {
    uint32_t a;
    asm("{ .reg .u64 t; cvta.to.shared.u64 t, %1; cvt.u32.u64 %0, t; }" : "=r"(a) : "l"(p));
    return a;
}
__device__ __forceinline__ void cp16(uint32_t saddr, const void* gaddr) {
    asm volatile("cp.async.cg.shared.global [%0], [%1], 16;" :: "r"(saddr), "l"(gaddr));
}
__device__ __forceinline__ void ldsm_x4(uint32_t* r, uint32_t addr) {
    asm volatile("ldmatrix.sync.aligned.m8n8.x4.shared.b16 {%0,%1,%2,%3}, [%4];"
                 : "=r"(r[0]), "=r"(r[1]), "=r"(r[2]), "=r"(r[3]) : "r"(addr));
}
__device__ __forceinline__ void ldsm_x4t(uint32_t* r, uint32_t addr) {
    asm volatile("ldmatrix.sync.aligned.m8n8.x4.trans.shared.b16 {%0,%1,%2,%3}, [%4];"
                 : "=r"(r[0]), "=r"(r[1]), "=r"(r[2]), "=r"(r[3]) : "r"(addr));
}
__device__ __forceinline__ void mma16816(float* d, const uint32_t* a, const uint32_t* b) {
    asm volatile(
        "mma.sync.aligned.m16n8k16.row.col.f32.bf16.bf16.f32 "
        "{%0,%1,%2,%3}, {%4,%5,%6,%7}, {%8,%9}, {%0,%1,%2,%3};"
        : "+f"(d[0]), "+f"(d[1]), "+f"(d[2]), "+f"(d[3])
        : "r"(a[0]), "r"(a[1]), "r"(a[2]), "r"(a[3]), "r"(b[0]), "r"(b[1]));
}
__device__ __forceinline__ void split4(float4 v, uint2& hp, uint2& lp) {
    __nv_bfloat16 h0 = __float2bfloat16(v.x);
    __nv_bfloat16 h1 = __float2bfloat16(v.y);
    __nv_bfloat16 h2 = __float2bfloat16(v.z);
    __nv_bfloat16 h3 = __float2bfloat16(v.w);
    __nv_bfloat16 l0 = __float2bfloat16(v.x - __bfloat162float(h0));
    __nv_bfloat16 l1 = __float2bfloat16(v.y - __bfloat162float(h1));
    __nv_bfloat16 l2 = __float2bfloat16(v.z - __bfloat162float(h2));
    __nv_bfloat16 l3 = __float2bfloat16(v.w - __bfloat162float(h3));
    __nv_bfloat162 hA = __halves2bfloat162(h0, h1);
    __nv_bfloat162 hB = __halves2bfloat162(h2, h3);
    __nv_bfloat162 lA = __halves2bfloat162(l0, l1);
    __nv_bfloat162 lB = __halves2bfloat162(l2, l3);
    hp.x = *(uint32_t*)&hA; hp.y = *(uint32_t*)&hB;
    lp.x = *(uint32_t*)&lA; lp.y = *(uint32_t*)&lB;
}
__device__ __forceinline__ void split2(float x, float y, uint32_t& hp, uint32_t& lp) {
    __nv_bfloat16 hx = __float2bfloat16(x), hy = __float2bfloat16(y);
    __nv_bfloat16 lx = __float2bfloat16(x - __bfloat162float(hx));
    __nv_bfloat16 ly = __float2bfloat16(y - __bfloat162float(hy));
    __nv_bfloat162 h = __halves2bfloat162(hx, hy);
    __nv_bfloat162 l = __halves2bfloat162(lx, ly);
    hp = *(uint32_t*)&h; lp = *(uint32_t*)&l;
}
__device__ __forceinline__ float4 h4_to_f4(uint2 u) {
    __half2 a = *(__half2*)&u.x, b = *(__half2*)&u.y;
    float2 fa = __half22float2(a), fb = __half22float2(b);
    return make_float4(fa.x, fa.y, fb.x, fb.y);
}

// ---------------- kernel 0: weight split + scratch clear + x->fp16 ----------------
__global__ void k_setup(const float* __restrict__ x,
                        const float* __restrict__ W0, const float* __restrict__ W1,
                        const float* __restrict__ W2, const float* __restrict__ W3,
                        const float* __restrict__ W4) {
    int b = blockIdx.x;
    int tid = threadIdx.x;
    if (b < 5) {
        const float* Ws[5] = {W0, W1, W2, W3, W4};
        const float* W = Ws[b];
        char* hi = &g_Wimg[b * 2 * TILE_BYTES];
        char* lo = hi + TILE_BYTES;
        for (int idx = tid; idx < 16384; idx += 256) {
            int k = idx >> 7, n = idx & 127;
            float v = W[k * 128 + n];
            __nv_bfloat16 h = __float2bfloat16(v);
            __nv_bfloat16 l = __float2bfloat16(v - __bfloat162float(h));
            uint32_t off = (uint32_t)(k * PITCH + n) * 2;
            *(__nv_bfloat16*)(hi + off) = h;
            *(__nv_bfloat16*)(lo + off) = l;
        }
    } else if (b < 55) {
        int i = (b - 5) * 256 + tid;
        if (i < 12500) ((int4*)g_cnt)[i] = make_int4(0, 0, 0, 0);
    } else if (b < 105) {
        int i = (b - 55) * 256 + tid;
        if (i < 12500) ((int4*)g_cur)[i] = make_int4(0, 0, 0, 0);
    } else if (b == 105) {
        if (tid < 16) g_tstate[tid] = 0ULL;
    } else {
        // x (fp32) -> g_H0 (fp16): 1,600,000 float4 groups
        int i = (b - 106) * 256 + tid;
        if (i < (N_NODES * F) / 4) {
            float4 v = ((const float4*)x)[i];
            __half2 a = __float22half2_rn(make_float2(v.x, v.y));
            __half2 c = __float22half2_rn(make_float2(v.z, v.w));
            uint2 u;
            u.x = *(uint32_t*)&a; u.y = *(uint32_t*)&c;
            ((uint2*)g_H0)[i] = u;
        }
    }
}

// ---------------- kernel 1: degree count (2 edges/thread) ----------------
__global__ void k_count(const int* __restrict__ ei, int e) {
    int i = (blockIdx.x * blockDim.x + threadIdx.x) * 2;
    if (i + 1 < e) {
        int d0 = ei[N_EDGES + i], d1 = ei[N_EDGES + i + 1];
        atomicAdd(&g_cnt[d0], 1);
        atomicAdd(&g_cnt[d1], 1);
    } else if (i < e) {
        atomicAdd(&g_cnt[ei[N_EDGES + i]], 1);
    }
}

// ---------------- kernel 2: single-pass scan + dinv ----------------
__global__ __launch_bounds__(1024) void k_scan(int n, int nb) {
    __shared__ int wsums[32];
    __shared__ int sh_total;
    __shared__ int sh_prefix;
    int tid = threadIdx.x, bid = blockIdx.x;
    int lane = tid & 31, w = tid >> 5;
    int base = bid * 4096 + tid * 4;
    int c0 = 0, c1 = 0, c2 = 0, c3 = 0;
    if (base < n) {
        int4 v = *(const int4*)&g_cnt[base];
        c0 = v.x; c1 = v.y; c2 = v.z; c3 = v.w;
        g_dinv[base]     = rsqrtf((float)(c0 + 1));
        g_dinv[base + 1] = rsqrtf((float)(c1 + 1));
        g_dinv[base + 2] = rsqrtf((float)(c2 + 1));
        g_dinv[base + 3] = rsqrtf((float)(c3 + 1));
    }
    int s = c0 + c1 + c2 + c3;
    int x = s;
#pragma unroll
    for (int o = 1; o < 32; o <<= 1) {
        int y = __shfl_up_sync(0xffffffffu, x, o);
        if (lane >= o) x += y;
    }
    if (lane == 31) wsums[w] = x;
    __syncthreads();
    if (w == 0) {
        int ws = wsums[lane];
        int xs = ws;
#pragma unroll
        for (int o = 1; o < 32; o <<= 1) {
            int y = __shfl_up_sync(0xffffffffu, xs, o);
            if (lane >= o) xs += y;
        }
        wsums[lane] = xs - ws;
        if (lane == 31) sh_total = xs;
    }
    __syncthreads();
    int excl = x - s + wsums[w];
    int total = sh_total;
    if (tid == 0) {
        int pre = 0;
        if (bid == 0) {
            atomicExch(&g_tstate[0], (2ULL << 32) | (unsigned)total);
        } else {
            atomicExch(&g_tstate[bid], (1ULL << 32) | (unsigned)total);
            int i = bid - 1;
            while (1) {
                unsigned long long v = atomicAdd(&g_tstate[i], 0ULL);
                unsigned f = (unsigned)(v >> 32);
                if (f == 0) continue;
                pre += (int)(unsigned)v;
                if (f == 2) break;
                i--;
            }
            atomicExch(&g_tstate[bid], (2ULL << 32) | (unsigned)(pre + total));
        }
        sh_prefix = pre;
        if (bid == nb - 1) g_rowstart[n] = pre + total;
    }
    __syncthreads();
    int run = sh_prefix + excl;
    if (base < n) {
        g_rowstart[base]     = run;
        g_rowstart[base + 1] = run + c0;
        g_rowstart[base + 2] = run + c0 + c1;
        g_rowstart[base + 3] = run + c0 + c1 + c2;
    }
}

// ---------------- kernel 3: CSR fill (2 edges/thread) ----------------
__global__ void k_fill(const int* __restrict__ ei, int e) {
    int i = (blockIdx.x * blockDim.x + threadIdx.x) * 2;
    if (i + 1 < e) {
        int d0 = ei[N_EDGES + i], d1 = ei[N_EDGES + i + 1];
        int s0 = ei[i], s1 = ei[i + 1];
        int p0 = atomicAdd(&g_cur[d0], 1);
        int p1 = atomicAdd(&g_cur[d1], 1);
        g_csr[g_rowstart[d0] + p0] = s0;
        g_csr[g_rowstart[d1] + p1] = s1;
    } else if (i < e) {
        int d = ei[N_EDGES + i];
        int p = atomicAdd(&g_cur[d], 1);
        g_csr[g_rowstart[d] + p] = ei[i];
    }
}

// ---------------- SpMM: split-tile output = Â H (fp16 H, warp per row) ----------------
__global__ __launch_bounds__(256) void k_spmm(const __half* __restrict__ H,
                                              char* __restrict__ T, int M) {
    int row = (blockIdx.x * blockDim.x + threadIdx.x) >> 5;   // == global row id
    if (row >= TILES * 128) return;
    int lane = threadIdx.x & 31;
    const uint2* H2 = (const uint2*)H;
    float4 acc = make_float4(0.f, 0.f, 0.f, 0.f);
    if (row < M) {
        float di = g_dinv[row];
        float4 h = h4_to_f4(H2[(size_t)row * 32 + lane]);
        acc.x = di * h.x; acc.y = di * h.y; acc.z = di * h.z; acc.w = di * h.w;
        int beg = g_rowstart[row], end = g_rowstart[row + 1];
        int j = beg;
        for (; j + 3 < end; j += 4) {
            int s0 = g_csr[j], s1 = g_csr[j + 1], s2 = g_csr[j + 2], s3 = g_csr[j + 3];
            float w0 = g_dinv[s0], w1 = g_dinv[s1], w2 = g_dinv[s2], w3 = g_dinv[s3];
            float4 v0 = h4_to_f4(H2[(size_t)s0 * 32 + lane]);
            float4 v1 = h4_to_f4(H2[(size_t)s1 * 32 + lane]);
            float4 v2 = h4_to_f4(H2[(size_t)s2 * 32 + lane]);
            float4 v3 = h4_to_f4(H2[(size_t)s3 * 32 + lane]);
            acc.x += w0 * v0.x + w1 * v1.x + w2 * v2.x + w3 * v3.x;
            acc.y += w0 * v0.y + w1 * v1.y + w2 * v2.y + w3 * v3.y;
            acc.z += w0 * v0.z + w1 * v1.z + w2 * v2.z + w3 * v3.z;
            acc.w += w0 * v0.w + w1 * v1.w + w2 * v2.w + w3 * v3.w;
        }
        for (; j < end; j++) {
            int s0 = g_csr[j];
            float w0 = g_dinv[s0];
            float4 v0 = h4_to_f4(H2[(size_t)s0 * 32 + lane]);
            acc.x += w0 * v0.x; acc.y += w0 * v0.y;
            acc.z += w0 * v0.z; acc.w += w0 * v0.w;
        }
        acc.x *= di; acc.y *= di; acc.z *= di; acc.w *= di;
    }
    int tile = row >> 7, rr = row & 127;
    char* tbase = T + (size_t)tile * (2 * TILE_BYTES);
    uint2 hp, lp;
    split4(acc, hp, lp);
    uint32_t off = (uint32_t)(rr * PITCH + lane * 4) * 2;
    *(uint2*)(tbase + off) = hp;
    *(uint2*)(tbase + TILE_BYTES + off) = lp;
}

// ================= persistent GEMM over split tiles =================
// OUT: 0 = fp16 C (GCN layers 1,2)  1 = split tiles (layer 3, MLP1)  2 = fused head
#define SM_BIAS 0
#define SM_WF3  512
#define SM_BF3  (512 + 8192)
#define SM_A0   8768
#define SM_A1   (SM_A0 + 2 * TILE_BYTES)   // 78400
#define SM_W    (SM_A1 + 2 * TILE_BYTES)   // 148032
#define SM_TOTAL (SM_W + 2 * TILE_BYTES)   // 217664

template<int OUT>
__global__ __launch_bounds__(256, 1) void k_gemm(
    const char* __restrict__ Tin, const char* __restrict__ Wimg,
    const float* __restrict__ bias,
    __half* __restrict__ Ch, char* __restrict__ Tout, int M,
    const float* __restrict__ Wf3, const float* __restrict__ bf3,
    float* __restrict__ out)
{
    extern __shared__ char smem[];
    uint32_t sb = smem_u32(smem);
    int tid = threadIdx.x;
    int wid = tid >> 5, lane = tid & 31;

    if (tid < 32) ((float4*)(smem + SM_BIAS))[tid] = ((const float4*)bias)[tid];
    if (OUT == 2) {
        for (int i = tid; i < 512; i += 256)
            ((float4*)(smem + SM_WF3))[i] = ((const float4*)Wf3)[i];
        if (tid < 16) ((float*)(smem + SM_BF3))[tid] = bf3[tid];
    }

    // W hi/lo resident
    for (int i = tid; i < (2 * TILE_BYTES) / 16; i += 256)
        cp16(sb + SM_W + i * 16, Wimg + i * 16);
    asm volatile("cp.async.commit_group;");

    int t = blockIdx.x;
    // prologue: prefetch first tile into A0
    for (int i = tid; i < (2 * TILE_BYTES) / 16; i += 256)
        cp16(sb + SM_A0 + i * 16, Tin + (size_t)t * (2 * TILE_BYTES) + i * 16);
    asm volatile("cp.async.commit_group;");

    int wm = wid >> 1, wn = wid & 1;
    int rsub = (lane & 7) + ((lane & 8) ? 8 : 0);
    int csub = (lane & 16) ? 8 : 0;
    uint32_t aoff0 = (uint32_t)((wm * 32 + rsub) * PITCH + csub) * 2;
    uint32_t aoff1 = aoff0 + (uint32_t)(16 * PITCH * 2);
    uint32_t wbase = sb + SM_W + (uint32_t)(rsub * PITCH + wn * 64 + csub) * 2;
    const uint32_t WLO = TILE_BYTES;
    const uint32_t KROW = 16 * PITCH * 2;

    int p = 0;
    for (; t < TILES; t += GGRID) {
        __syncthreads();   // all warps done with buffer p^1 (prev MMA / Ys use)

        int tn = t + GGRID;
        uint32_t nbuf = (p == 0) ? (sb + SM_A1) : (sb + SM_A0);
        if (tn < TILES) {
            for (int i = tid; i < (2 * TILE_BYTES) / 16; i += 256)
                cp16(nbuf + i * 16, Tin + (size_t)tn * (2 * TILE_BYTES) + i * 16);
        }
        asm volatile("cp.async.commit_group;");
        asm volatile("cp.async.wait_group 1;" ::: "memory");
        __syncthreads();   // tile t's data visible to all warps

        uint32_t ab = (p == 0) ? (sb + SM_A0) : (sb + SM_A1);
        uint32_t a0 = ab + aoff0, a1 = ab + aoff1;
        uint32_t l0a = a0 + TILE_BYTES, l1a = a1 + TILE_BYTES;

        float acc[2][4][8];
#pragma unroll
        for (int m = 0; m < 2; m++)
#pragma unroll
            for (int g = 0; g < 4; g++)
#pragma unroll
                for (int j = 0; j < 8; j++) acc[m][g][j] = 0.f;

#pragma unroll
        for (int kc = 0; kc < 8; kc++) {
            uint32_t ah[2][4], al[2][4];
            ldsm_x4(ah[0], a0 + kc * 32);
            ldsm_x4(ah[1], a1 + kc * 32);
            ldsm_x4(al[0], l0a + kc * 32);
            ldsm_x4(al[1], l1a + kc * 32);
            uint32_t bh[4][4], bl[4][4];
#pragma unroll
            for (int g = 0; g < 4; g++) ldsm_x4t(bh[g], wbase + kc * KROW + g * 32);
#pragma unroll
            for (int g = 0; g < 4; g++) ldsm_x4t(bl[g], wbase + WLO + kc * KROW + g * 32);
#pragma unroll
            for (int g = 0; g < 4; g++)
#pragma unroll
                for (int m = 0; m < 2; m++) {
                    mma16816(&acc[m][g][0], ah[m], &bh[g][0]);
                    mma16816(&acc[m][g][4], ah[m], &bh[g][2]);
                }
#pragma unroll
            for (int g = 0; g < 4; g++)
#pragma unroll
                for (int m = 0; m < 2; m++) {
                    mma16816(&acc[m][g][0], ah[m], &bl[g][0]);
                    mma16816(&acc[m][g][4], ah[m], &bl[g][2]);
                }
#pragma unroll
            for (int g = 0; g < 4; g++)
#pragma unroll
                for (int m = 0; m < 2; m++) {
                    mma16816(&acc[m][g][0], al[m], &bh[g][0]);
                    mma16816(&acc[m][g][4], al[m], &bh[g][2]);
                }
        }

        const float* bias_s = (const float*)(smem + SM_BIAS);
        int rq = lane >> 2;
        int cq = (lane & 3) * 2;
        int rowBase = t * 128;

        if (OUT == 0) {
            // fp16 output (feeds next SpMM)
#pragma unroll
            for (int m = 0; m < 2; m++) {
                int r0 = rowBase + wm * 32 + m * 16 + rq;
#pragma unroll
                for (int g = 0; g < 4; g++) {
#pragma unroll
                    for (int h = 0; h < 2; h++) {
                        int c = wn * 64 + g * 16 + h * 8 + cq;
                        float bx = bias_s[c], by = bias_s[c + 1];
                        float* base = &acc[m][g][h * 4];
                        if (r0 < M) {
                            __half2 v = __float22half2_rn(make_float2(
                                fmaxf(base[0] + bx, 0.f), fmaxf(base[1] + by, 0.f)));
                            *(uint32_t*)&Ch[(size_t)r0 * 128 + c] = *(uint32_t*)&v;
                        }
                        if (r0 + 8 < M) {
                            __half2 v = __float22half2_rn(make_float2(
                                fmaxf(base[2] + bx, 0.f), fmaxf(base[3] + by, 0.f)));
                            *(uint32_t*)&Ch[(size_t)(r0 + 8) * 128 + c] = *(uint32_t*)&v;
                        }
                    }
                }
            }
        } else if (OUT == 1) {
            // split-tile output (feeds next GEMM); write all rows incl. padding
            char* tb = Tout + (size_t)t * (2 * TILE_BYTES);
#pragma unroll
            for (int m = 0; m < 2; m++) {
                int rl = wm * 32 + m * 16 + rq;
#pragma unroll
                for (int g = 0; g < 4; g++) {
#pragma unroll
                    for (int h = 0; h < 2; h++) {
                        int c = wn * 64 + g * 16 + h * 8 + cq;
                        float bx = bias_s[c], by = bias_s[c + 1];
                        float* base = &acc[m][g][h * 4];
                        uint32_t hp, lp;
                        split2(fmaxf(base[0] + bx, 0.f), fmaxf(base[1] + by, 0.f), hp, lp);
                        uint32_t off = (uint32_t)(rl * PITCH + c) * 2;
                        *(uint32_t*)(tb + off) = hp;
                        *(uint32_t*)(tb + TILE_BYTES + off) = lp;
                        split2(fmaxf(base[2] + bx, 0.f), fmaxf(base[3] + by, 0.f), hp, lp);
                        off = (uint32_t)((rl + 8) * PITCH + c) * 2;
                        *(uint32_t*)(tb + off) = hp;
                        *(uint32_t*)(tb + TILE_BYTES + off) = lp;
                    }
                }
            }
        } else {
            // fused head: Ys into buffer p (just finished reading it)
            __syncthreads();
            float* Ys = (float*)(smem + ((p == 0) ? SM_A0 : SM_A1));
#pragma unroll
            for (int m = 0; m < 2; m++) {
                int rl = wm * 32 + m * 16 + rq;
#pragma unroll
                for (int g = 0; g < 4; g++) {
#pragma unroll
                    for (int h = 0; h < 2; h++) {
                        int c = wn * 64 + g * 16 + h * 8 + cq;
                        float bx = bias_s[c], by = bias_s[c + 1];
                        float* base = &acc[m][g][h * 4];
                        float2 v;
                        v.x = fmaxf(base[0] + bx, 0.f);
                        v.y = fmaxf(base[1] + by, 0.f);
                        *(float2*)&Ys[rl * 128 + c] = v;
                        float2 v2;
                        v2.x = fmaxf(base[2] + bx, 0.f);
                        v2.y = fmaxf(base[3] + by, 0.f);
                        *(float2*)&Ys[(rl + 8) * 128 + c] = v2;
                    }
                }
            }
            __syncthreads();
            const float* Wfs = (const float*)(smem + SM_WF3);
            const float* bfs = (const float*)(smem + SM_BF3);
            int hr = tid >> 4, hc = tid & 15;
#pragma unroll
            for (int pz = 0; pz < 8; pz++) {
                int r = pz * 16 + hr;
                float a2 = bfs[hc];
#pragma unroll 16
                for (int k = 0; k < 128; k++) a2 += Ys[r * 128 + k] * Wfs[k * 16 + hc];
                float mx = a2;
#pragma unroll
                for (int o = 8; o > 0; o >>= 1) mx = fmaxf(mx, __shfl_xor_sync(0xffffffffu, mx, o));
                float e = expf(a2 - mx);
                float ssum = e;
#pragma unroll
                for (int o = 8; o > 0; o >>= 1) ssum += __shfl_xor_sync(0xffffffffu, ssum, o);
                float res = a2 - mx - logf(ssum);
                int grow = rowBase + r;
                if (grow < M) out[(size_t)grow * 16 + hc] = res;
            }
        }
        p ^= 1;
    }
}

// ---------------- launch ----------------
extern "C" void kernel_launch(void* const* d_in, const int* in_sizes, int n_in,
                              void* d_out, int out_size) {
    const float* x   = (const float*)d_in[0];
    const int*   ei  = (const int*)d_in[1];
    const float* W1  = (const float*)d_in[3];
    const float* b1  = (const float*)d_in[4];
    const float* W2  = (const float*)d_in[5];
    const float* b2  = (const float*)d_in[6];
    const float* W3  = (const float*)d_in[7];
    const float* b3  = (const float*)d_in[8];
    const float* Wf1 = (const float*)d_in[9];
    const float* bf1 = (const float*)d_in[10];
    const float* Wf2 = (const float*)d_in[11];
    const float* bf2 = (const float*)d_in[12];
    const float* Wf3 = (const float*)d_in[13];
    const float* bf3 = (const float*)d_in[14];
    float* out = (float*)d_out;

    const int N = N_NODES;
    const int E = N_EDGES;

    __half* H0; __half* H1; char* T; char* T2; char* wimg;
    cudaGetSymbolAddress((void**)&H0, g_H0);
    cudaGetSymbolAddress((void**)&H1, g_H1);
    cudaGetSymbolAddress((void**)&T,  g_T);
    cudaGetSymbolAddress((void**)&T2, g_T2);
    cudaGetSymbolAddress((void**)&wimg, g_Wimg);

    static int attr_done = 0;
    if (!attr_done) {
        cudaFuncSetAttribute(k_gemm<0>, cudaFuncAttributeMaxDynamicSharedMemorySize, SM_TOTAL);
        cudaFuncSetAttribute(k_gemm<1>, cudaFuncAttributeMaxDynamicSharedMemorySize, SM_TOTAL);
        cudaFuncSetAttribute(k_gemm<2>, cudaFuncAttributeMaxDynamicSharedMemorySize, SM_TOTAL);
        attr_done = 1;
    }

    const size_t IMG = 2 * (size_t)TILE_BYTES;
    const int spmmBlocks = (TILES * 128 * 32 + 255) / 256;   // 6256

    k_setup<<<106 + (N * F / 4 + 255) / 256, 256>>>(x, W1, W2, W3, Wf1, Wf2);   // 0
    k_count<<<(E / 2 + 255) / 256, 256>>>(ei, E);                                // 1
    k_scan<<<13, 1024>>>(N, 13);                                                 // 2
    k_fill<<<(E / 2 + 255) / 256, 256>>>(ei, E);                                 // 3

    k_spmm<<<spmmBlocks, 256>>>(H0, T, N);                                       // 4
    k_gemm<0><<<GGRID, 256, SM_TOTAL>>>(T, wimg + 0 * IMG, b1, H1, nullptr, N,
                                        nullptr, nullptr, nullptr);              // 5 <- ncu
    k_spmm<<<spmmBlocks, 256>>>(H1, T, N);                                       // 6
    k_gemm<0><<<GGRID, 256, SM_TOTAL>>>(T, wimg + 1 * IMG, b2, H0, nullptr, N,
                                        nullptr, nullptr, nullptr);              // 7
    k_spmm<<<spmmBlocks, 256>>>(H0, T, N);                                       // 8
    k_gemm<1><<<GGRID, 256, SM_TOTAL>>>(T, wimg + 2 * IMG, b3, nullptr, T2, N,
                                        nullptr, nullptr, nullptr);              // 9
    k_gemm<1><<<GGRID, 256, SM_TOTAL>>>(T2, wimg + 3 * IMG, bf1, nullptr, T, N,
                                        nullptr, nullptr, nullptr);              // 10
    k_gemm<2><<<GGRID, 256, SM_TOTAL>>>(T, wimg + 4 * IMG, bf2, nullptr, nullptr, N,
                                        Wf3, bf3, out);                          // 11
}